// round 14
// baseline (speedup 1.0000x reference)
#include <cuda_runtime.h>
#include <stdint.h>

// Problem constants
#define BB_  4
#define SS_  8192
#define EE_  1024
#define HH_  16
#define DD_  64
#define SP_  512
#define MQKV (BB_*SS_)
#define MOUT (BB_*SP_)

// Scratch: q/k/v/ctx hold tf32 bit patterns; weights pre-converted AND
// pre-swizzled into mma-fragment order.
__device__ uint32_t g_q[BB_*HH_*SP_*DD_];     // [B,H,S',D] tf32 bits
__device__ uint32_t g_k[BB_*HH_*SP_*DD_];
__device__ uint32_t g_v[BB_*HH_*SP_*DD_];
__device__ uint32_t g_ctx[BB_*SP_*EE_];       // [B,S',E]  tf32 bits
__device__ uint32_t g_wqkv[192*EE_];          // fragment-ordered [Wq;Wk;Wv]
__device__ uint32_t g_wo[EE_*EE_];            // fragment-ordered Wo (128-wide n-blocks)

// ---------------------------------------------------------------------------
// helpers
// ---------------------------------------------------------------------------
__device__ __forceinline__ uint32_t f2tf32(float f) {
    uint32_t u;
    asm("cvt.rna.tf32.f32 %0, %1;" : "=r"(u) : "f"(f));
    return u;
}

__device__ __forceinline__ void mma_tf32(float c[4], const uint32_t a[4], const uint32_t b[2]) {
    asm volatile(
        "mma.sync.aligned.m16n8k8.row.col.f32.tf32.tf32.f32 "
        "{%0,%1,%2,%3}, {%4,%5,%6,%7}, {%8,%9}, {%0,%1,%2,%3};\n"
        : "+f"(c[0]), "+f"(c[1]), "+f"(c[2]), "+f"(c[3])
        : "r"(a[0]), "r"(a[1]), "r"(a[2]), "r"(a[3]), "r"(b[0]), "r"(b[1]));
}

__device__ __forceinline__ void ldsm_x4(uint32_t r[4], uint32_t addr) {
    asm volatile("ldmatrix.sync.aligned.m8n8.x4.shared.b16 {%0,%1,%2,%3}, [%4];"
                 : "=r"(r[0]), "=r"(r[1]), "=r"(r[2]), "=r"(r[3]) : "r"(addr));
}

__device__ __forceinline__ uint32_t smem_u32(const void* p) {
    return (uint32_t)__cvta_generic_to_shared(p);
}
#define CP16(dst, src) asm volatile("cp.async.cg.shared.global [%0], [%1], 16;\n" :: "r"(dst), "l"(src))
#define CP_COMMIT()    asm volatile("cp.async.commit_group;\n" ::: "memory")
#define CP_WAIT1()     asm volatile("cp.async.wait_group 1;\n" ::: "memory")
#define CP_WAIT2()     asm volatile("cp.async.wait_group 2;\n" ::: "memory")

#define S20 20   // smem row stride (80B): LDSM phases conflict-free, 16B-aligned

// Fragment-pair tile: 16 n-rows x 8 k, 128 u32.
__device__ __forceinline__ int frag_idx(int n16, int k8) {
    return ((n16 & 7) * 4 + (k8 & 3)) * 4 + ((n16 >> 3) << 1) + (k8 >> 2);
}

// ---------------------------------------------------------------------------
// Kernel 0: pre-convert + pre-swizzle weights (once per launch, ~5us)
// ---------------------------------------------------------------------------
__global__ __launch_bounds__(256)
void cvt_weights(const float* __restrict__ Wq, const float* __restrict__ Wk,
                 const float* __restrict__ Wv, const float* __restrict__ Wo)
{
    const int idx = blockIdx.x * 256 + threadIdx.x;   // 0..65535
    const int row = idx >> 10;
    const int k   = idx & 1023;
    const int it  = k >> 4;
    const int ks  = (k >> 3) & 1;
    const int k8  = k & 7;

    {
        const float* Ws[3] = { Wq, Wk, Wv };
        #pragma unroll
        for (int mat = 0; mat < 3; mat++) {
            int n = mat * 64 + row;
            int addr = ((it * 2 + ks) * 12 + (n >> 4)) * 128 + frag_idx(n & 15, k8);
            g_wqkv[addr] = f2tf32(Ws[mat][row * 1024 + k]);
        }
    }
    #pragma unroll
    for (int j = 0; j < 16; j++) {
        int e  = idx + j * 65536;
        int n  = e >> 10;
        int kk = e & 1023;
        int it2 = kk >> 4, ks2 = (kk >> 3) & 1, k82 = kk & 7;
        int nb = n >> 7, nn = n & 127;
        int addr = (((nb * 64 + it2) * 2 + ks2) * 8 + (nn >> 4)) * 128 + frag_idx(nn & 15, k82);
        g_wo[addr] = f2tf32(Wo[(size_t)n * 1024 + kk]);
    }
}

// ---------------------------------------------------------------------------
// Kernel 1: fused QKV projection.  BM=64, BN=192, BK=16, 256 thr / 8 warps,
// warp tile 32m x 48n.  4-stage cp.async (wait_group 2).  Grid 512.
// ---------------------------------------------------------------------------
#define QKV_ASTG (64 * S20)    // 1280 u32
#define QKV_BSTG 3072          // u32
#define QKV_SMEM ((4 * QKV_ASTG + 4 * QKV_BSTG) * 4)   // 69.6 KB

__global__ __launch_bounds__(256)
void qkv_mma(const float* __restrict__ x,
             const float* __restrict__ bq, const float* __restrict__ bk,
             const float* __restrict__ bv)
{
    extern __shared__ uint32_t sm[];
    uint32_t* As = sm;                      // 4 stages of [64][S20]
    uint32_t* Bs = sm + 4 * QKV_ASTG;       // 4 stages of 3072 (fragment order)

    const int tid  = threadIdx.x;
    const int warp = tid >> 5;
    const int lane = tid & 31;
    const int wm   = warp >> 2;           // 0..1
    const int wn   = warp & 3;            // 0..3
    const int m0   = blockIdx.x * 64;
    const int lq   = lane >> 2;
    const int lr   = lane & 3;

    const int lt       = lane >> 3;
    const int lrw      = lane & 7;
    const int arow_off = (lt & 1) * 8 + lrw;
    const int akoff    = (lt >> 1) * 4;
    uint32_t a_ldsm[4];
    #pragma unroll
    for (int s = 0; s < 4; s++)
        a_ldsm[s] = smem_u32(&As[s * QKV_ASTG + (wm * 32 + arow_off) * S20 + akoff]);

    const int arow = tid >> 2;
    const int ac4  = (tid & 3) * 4;
    const float* a_src = x + (size_t)(m0 + arow) * 1024 + ac4;
    uint32_t a_dst[4];
    #pragma unroll
    for (int s = 0; s < 4; s++)
        a_dst[s] = smem_u32(&As[s * QKV_ASTG + arow * S20 + ac4]);

    uint32_t b_dst[3][4];
    #pragma unroll
    for (int s = 0; s < 4; s++)
        #pragma unroll
        for (int t = 0; t < 3; t++)
            b_dst[t][s] = smem_u32(&Bs[s * QKV_BSTG + (t * 256 + tid) * 4]);

    float acc[2][6][4];
    #pragma unroll
    for (int mt = 0; mt < 2; mt++)
        #pragma unroll
        for (int nt = 0; nt < 6; nt++)
            #pragma unroll
            for (int e = 0; e < 4; e++) acc[mt][nt][e] = 0.f;

    #pragma unroll
    for (int s = 0; s < 3; s++) {
        CP16(a_dst[s], a_src + s * 16);
        #pragma unroll
        for (int t = 0; t < 3; t++)
            CP16(b_dst[t][s], g_wqkv + s * QKV_BSTG + (t * 256 + tid) * 4);
        CP_COMMIT();
    }

    for (int it = 0; it < 64; ++it) {
        CP_WAIT2();
        __syncthreads();

        if (it + 3 < 64) {
            int s = (it + 3) & 3;
            CP16(a_dst[s], a_src + (it + 3) * 16);
            #pragma unroll
            for (int t = 0; t < 3; t++)
                CP16(b_dst[t][s], g_wqkv + (it + 3) * QKV_BSTG + (t * 256 + tid) * 4);
        }
        CP_COMMIT();

        const int cur = it & 3;
        const uint32_t* Bc = Bs + cur * QKV_BSTG;
        const uint32_t  Ab = a_ldsm[cur];

        #pragma unroll
        for (int ks = 0; ks < 2; ks++) {
            uint32_t af[2][4];
            #pragma unroll
            for (int mt = 0; mt < 2; mt++) {
                uint32_t raw[4];
                ldsm_x4(raw, Ab + (uint32_t)((mt * 16 * S20 + ks * 8) * 4));
                af[mt][0] = f2tf32(__uint_as_float(raw[0]));
                af[mt][1] = f2tf32(__uint_as_float(raw[1]));
                af[mt][2] = f2tf32(__uint_as_float(raw[2]));
                af[mt][3] = f2tf32(__uint_as_float(raw[3]));
            }
            #pragma unroll
            for (int pl = 0; pl < 3; pl++) {
                uint4 bv = *(const uint4*)&Bc[(ks * 12 + wn * 3 + pl) * 128 + lane * 4];
                uint32_t bfe[2] = { bv.x, bv.y };
                uint32_t bfo[2] = { bv.z, bv.w };
                mma_tf32(acc[0][2*pl  ], af[0], bfe);
                mma_tf32(acc[1][2*pl  ], af[1], bfe);
                mma_tf32(acc[0][2*pl+1], af[0], bfo);
                mma_tf32(acc[1][2*pl+1], af[1], bfo);
            }
        }
    }

    #pragma unroll
    for (int mt = 0; mt < 2; mt++) {
        #pragma unroll
        for (int half = 0; half < 2; half++) {
            int m  = m0 + wm * 32 + mt * 16 + half * 8 + lq;
            int bb = m >> 13;
            int s  = m & 8191;
            int sp = s >> 4;
            int h  = s & 15;
            size_t rowoff = ((size_t)(bb * 16 + h) * 512 + sp) * 64;
            #pragma unroll
            for (int nt = 0; nt < 6; nt++) {
                int n   = wn * 48 + nt * 8 + 2 * lr;
                int mat = n >> 6;
                int nn  = n & 63;
                uint32_t* dst = (mat == 0) ? g_q : (mat == 1 ? g_k : g_v);
                const float* bias = (mat == 0) ? bq : (mat == 1 ? bk : bv);
                uint2 v;
                v.x = f2tf32(acc[mt][nt][half * 2 + 0] + bias[nn]);
                v.y = f2tf32(acc[mt][nt][half * 2 + 1] + bias[nn + 1]);
                *(uint2*)(dst + rowoff + nn) = v;
            }
        }
    }
}

// ---------------------------------------------------------------------------
// Kernel 2: attention (R12 version — K-frags via ldmatrix.x4).
// ---------------------------------------------------------------------------
#define KSTR 68
#define VSTR 72

__global__ __launch_bounds__(256)
void attn_mma()
{
    __shared__ __align__(16) uint32_t Ks[64 * KSTR];
    __shared__ __align__(16) uint32_t Vs[64 * VSTR];

    const int bh   = blockIdx.x;
    const int qt   = blockIdx.y;
    const int tid  = threadIdx.x;
    const int warp = tid >> 5;
    const int lane = tid & 31;
    const int lq   = lane >> 2;
    const int lr   = lane & 3;

    const int g     = lane >> 3;
    const int rg    = lane & 7;
    const int sub_n = (g >> 1) * 8 + rg;
    const int koff  = (g & 1) * 4;
    const uint32_t k_ldsm = smem_u32(&Ks[sub_n * KSTR + koff]);

    const uint32_t* qbase = g_q + ((size_t)bh * 512 + qt * 128 + warp * 16) * 64;
    uint32_t qa[8][4];
    #pragma unroll
    for (int ks = 0; ks < 8; ks++) {
        qa[ks][0] = __float_as_uint(__uint_as_float(qbase[(size_t)lq       * 64 + ks * 8 + lr    ]) * 0.125f);
        qa[ks][1] = __float_as_uint(__uint_as_float(qbase[(size_t)(lq + 8) * 64 + ks * 8 + lr    ]) * 0.125f);
        qa[ks][2] = __float_as_uint(__uint_as_float(qbase[(size_t)lq       * 64 + ks * 8 + lr + 4]) * 0.125f);
        qa[ks][3] = __float_as_uint(__uint_as_float(qbase[(size_t)(lq + 8) * 64 + ks * 8 + lr + 4]) * 0.125f);
    }

    float o[8][4];
    #pragma unroll
    for (int nt = 0; nt < 8; nt++)
        #pragma unroll
        for (int e = 0; e < 4; e++) o[nt][e] = 0.f;
    float lsum0 = 0.f, lsum1 = 0.f;

    const uint32_t* kb = g_k + (size_t)bh * 512 * 64;
    const uint32_t* vb = g_v + (size_t)bh * 512 * 64;

    for (int kt = 0; kt < 8; kt++) {
        __syncthreads();
        #pragma unroll
        for (int i = 0; i < 4; i++) {
            int idx = tid + i * 256;
            int row = idx >> 4, c4 = (idx & 15) << 2;
            *(uint4*)(Ks + row * KSTR + c4) = *(const uint4*)(kb + (size_t)kt * 4096 + idx * 4);
            *(uint4*)(Vs + row * VSTR + c4) = *(const uint4*)(vb + (size_t)kt * 4096 + idx * 4);
        }
        __syncthreads();

        float sc[8][4];
        #pragma unroll
        for (int nt = 0; nt < 8; nt++)
            sc[nt][0] = sc[nt][1] = sc[nt][2] = sc[nt][3] = 0.f;
        #pragma unroll
        for (int ks = 0; ks < 8; ks++) {
            #pragma unroll
            for (int ntp = 0; ntp < 4; ntp++) {
                uint32_t raw[4];
                ldsm_x4(raw, k_ldsm + (uint32_t)((ntp * 16 * KSTR + ks * 8) * 4));
                uint32_t bf0[2] = { raw[0], raw[1] };
                uint32_t bf1[2] = { raw[2], raw[3] };
                mma_tf32(sc[2*ntp    ], qa[ks], bf0);
                mma_tf32(sc[2*ntp + 1], qa[ks], bf1);
            }
        }

        #pragma unroll
        for (int nt = 0; nt < 8; nt++) {
            float p0 = __expf(sc[nt][0]), p1 = __expf(sc[nt][1]);
            float p2 = __expf(sc[nt][2]), p3 = __expf(sc[nt][3]);
            sc[nt][0] = p0; sc[nt][1] = p1; sc[nt][2] = p2; sc[nt][3] = p3;
            lsum0 += p0 + p1;
            lsum1 += p2 + p3;
        }

        #pragma unroll
        for (int ks = 0; ks < 8; ks++) {
            int src  = (lane & ~3) | (lr >> 1);
            float t0 = __shfl_sync(0xffffffffu, sc[ks][0], src);
            float t1 = __shfl_sync(0xffffffffu, sc[ks][1], src);
            float t2 = __shfl_sync(0xffffffffu, sc[ks][2], src);
            float t3 = __shfl_sync(0xffffffffu, sc[ks][3], src);
            float u0 = __shfl_sync(0xffffffffu, sc[ks][0], src + 2);
            float u1 = __shfl_sync(0xffffffffu, sc[ks][1], src + 2);
            float u2 = __shfl_sync(0xffffffffu, sc[ks][2], src + 2);
            float u3 = __shfl_sync(0xffffffffu, sc[ks][3], src + 2);
            uint32_t pa[4];
            pa[0] = f2tf32((lr & 1) ? t1 : t0);
            pa[1] = f2tf32((lr & 1) ? t3 : t2);
            pa[2] = f2tf32((lr & 1) ? u1 : u0);
            pa[3] = f2tf32((lr & 1) ? u3 : u2);
            #pragma unroll
            for (int ntd = 0; ntd < 8; ntd++) {
                uint32_t bf[2];
                bf[0] = Vs[(ks * 8 + lr    ) * VSTR + ntd * 8 + lq];
                bf[1] = Vs[(ks * 8 + lr + 4) * VSTR + ntd * 8 + lq];
                mma_tf32(o[ntd], pa, bf);
            }
        }
    }

    lsum0 += __shfl_xor_sync(0xffffffffu, lsum0, 1);
    lsum0 += __shfl_xor_sync(0xffffffffu, lsum0, 2);
    lsum1 += __shfl_xor_sync(0xffffffffu, lsum1, 1);
    lsum1 += __shfl_xor_sync(0xffffffffu, lsum1, 2);
    const float inv0 = 1.f / lsum0;
    const float inv1 = 1.f / lsum1;

    const int bb = bh >> 4, h = bh & 15;
    const int qrow0 = qt * 128 + warp * 16 + lq;
    uint32_t* out0 = g_ctx + ((size_t)(bb * 512 + qrow0)) * 1024 + h * 64;
    uint32_t* out1 = out0 + (size_t)8 * 1024;
    #pragma unroll
    for (int ntd = 0; ntd < 8; ntd++) {
        uint2 v0 = { f2tf32(o[ntd][0] * inv0), f2tf32(o[ntd][1] * inv0) };
        uint2 v1 = { f2tf32(o[ntd][2] * inv1), f2tf32(o[ntd][3] * inv1) };
        *(uint2*)(out0 + ntd * 8 + 2 * lr) = v0;
        *(uint2*)(out1 + ntd * 8 + 2 * lr) = v1;
    }
}

// ---------------------------------------------------------------------------
// Kernel 3: output projection.  BM=64, BN=128, BK=16, 256 thr / 8 warps,
// warp tile 32m x 32n (wm=warp>>2 in 0..1, wn=warp&3).  Grid 256 -> 2-3 CTAs/SM.
// A (ctx, tf32) -> LDSM.x4.  B (Wo) fragment-ordered -> LDS.128.
// ---------------------------------------------------------------------------
#define OP_ASTG (64 * S20)    // 1280 u32
#define OP_BSTG 2048          // u32
#define OP_SMEM ((3 * OP_ASTG + 3 * OP_BSTG) * 4)   // 39.9 KB

__global__ __launch_bounds__(256)
void outproj_mma(const float* __restrict__ bo, float* __restrict__ out)
{
    extern __shared__ uint32_t sm[];
    uint32_t* As = sm;
    uint32_t* Bs = sm + 3 * OP_ASTG;

    const int tid  = threadIdx.x;
    const int warp = tid >> 5;
    const int lane = tid & 31;
    const int wm   = warp >> 2;           // 0..1
    const int wn   = warp & 3;            // 0..3
    const int m0   = blockIdx.x * 64;
    const int nb   = blockIdx.y;          // 128-wide n block
    const int lq   = lane >> 2;
    const int lr   = lane & 3;

    const int lt       = lane >> 3;
    const int lrw      = lane & 7;
    const int arow_off = (lt & 1) * 8 + lrw;
    const int akoff    = (lt >> 1) * 4;
    uint32_t a_ldsm[3];
    #pragma unroll
    for (int s = 0; s < 3; s++)
        a_ldsm[s] = smem_u32(&As[s * OP_ASTG + (wm * 32 + arow_off) * S20 + akoff]);

    // A: 64x16 = 256 f4, 1 per thread
    const int arow = tid >> 2;
    const int ac4  = (tid & 3) * 4;
    const uint32_t* a_src = g_ctx + (size_t)(m0 + arow) * 1024 + ac4;
    uint32_t a_dst[3];
    #pragma unroll
    for (int s = 0; s < 3; s++)
        a_dst[s] = smem_u32(&As[s * OP_ASTG + arow * S20 + ac4]);

    // B: 512 f4, 2 per thread (chunks tid, 256+tid)
    uint32_t b_dst[2][3];
    #pragma unroll
    for (int s = 0; s < 3; s++)
        #pragma unroll
        for (int t = 0; t < 2; t++)
            b_dst[t][s] = smem_u32(&Bs[s * OP_BSTG + (t * 256 + tid) * 4]);
    const uint32_t* b_base = g_wo + (size_t)nb * 64 * OP_BSTG;

    float acc[2][4][4];
    #pragma unroll
    for (int mt = 0; mt < 2; mt++)
        #pragma unroll
        for (int nt = 0; nt < 4; nt++)
            #pragma unroll
            for (int e = 0; e < 4; e++) acc[mt][nt][e] = 0.f;

    #pragma unroll
    for (int s = 0; s < 2; s++) {
        CP16(a_dst[s], a_src + s * 16);
        #pragma unroll
        for (int t = 0; t < 2; t++)
            CP16(b_dst[t][s], b_base + s * OP_BSTG + (t * 256 + tid) * 4);
        CP_COMMIT();
    }

    for (int it = 0; it < 64; ++it) {
        CP_WAIT1();
        __syncthreads();

        if (it + 2 < 64) {
            int s = (it + 2) % 3;
            CP16(a_dst[s], a_src + (it + 2) * 16);
            #pragma unroll
            for (int t = 0; t < 2; t++)
                CP16(b_dst[t][s], b_base + (size_t)(it + 2) * OP_BSTG + (t * 256 + tid) * 4);
        }
        CP_COMMIT();

        const int cur = it % 3;
        const uint32_t* Bc = Bs + cur * OP_BSTG;
        const uint32_t  Ab = a_ldsm[cur];

        #pragma unroll
        for (int ks = 0; ks < 2; ks++) {
            uint32_t af[2][4];
            #pragma unroll
            for (int mt = 0; mt < 2; mt++)
                ldsm_x4(af[mt], Ab + (uint32_t)((mt * 16 * S20 + ks * 8) * 4));
            #pragma unroll
            for (int pl = 0; pl < 2; pl++) {
                uint4 bv = *(const uint4*)&Bc[(ks * 8 + wn * 2 + pl) * 128 + lane * 4];
                uint32_t bfe[2] = { bv.x, bv.y };
                uint32_t bfo[2] = { bv.z, bv.w };
                mma_tf32(acc[0][2*pl  ], af[0], bfe);
                mma_tf32(acc[1][2*pl  ], af[1], bfe);
                mma_tf32(acc[0][2*pl+1], af[0], bfo);
                mma_tf32(acc[1][2*pl+1], af[1], bfo);
            }
        }
    }

    #pragma unroll
    for (int mt = 0; mt < 2; mt++) {
        #pragma unroll
        for (int half = 0; half < 2; half++) {
            int m = m0 + wm * 32 + mt * 16 + half * 8 + lq;
            float* rowp = out + (size_t)m * 1024 + nb * 128;
            #pragma unroll
            for (int nt = 0; nt < 4; nt++) {
                int n = wn * 32 + nt * 8 + 2 * lr;
                float2 v;
                v.x = acc[mt][nt][half * 2 + 0] + bo[nb * 128 + n];
                v.y = acc[mt][nt][half * 2 + 1] + bo[nb * 128 + n + 1];
                *(float2*)(rowp + n) = v;
            }
        }
    }
}

// ---------------------------------------------------------------------------
extern "C" void kernel_launch(void* const* d_in, const int* in_sizes, int n_in,
                              void* d_out, int out_size)
{
    const float* x  = (const float*)d_in[0];
    const float* Wq = (const float*)d_in[1];
    const float* bq = (const float*)d_in[2];
    const float* Wk = (const float*)d_in[3];
    const float* bk = (const float*)d_in[4];
    const float* Wv = (const float*)d_in[5];
    const float* bv = (const float*)d_in[6];
    const float* Wo = (const float*)d_in[7];
    const float* bo = (const float*)d_in[8];
    float* out = (float*)d_out;

    static bool attr_done = false;
    if (!attr_done) {
        cudaFuncSetAttribute(qkv_mma, cudaFuncAttributeMaxDynamicSharedMemorySize, QKV_SMEM);
        cudaFuncSetAttribute(outproj_mma, cudaFuncAttributeMaxDynamicSharedMemorySize, OP_SMEM);
        attr_done = true;
    }

    cvt_weights<<<256, 256>>>(Wq, Wk, Wv, Wo);

    qkv_mma<<<MQKV / 64, 256, QKV_SMEM>>>(x, bq, bk, bv);

    dim3 g2(BB_ * HH_, SP_ / 128);
    attn_mma<<<g2, 256>>>();

    dim3 g3(MOUT / 64, EE_ / 128);
    outproj_mma<<<g3, 256, OP_SMEM>>>(bo, out);
}

// round 15
// speedup vs baseline: 1.1199x; 1.1199x over previous
#include <cuda_runtime.h>
#include <stdint.h>

// Problem constants
#define BB_  4
#define SS_  8192
#define EE_  1024
#define HH_  16
#define DD_  64
#define SP_  512
#define MQKV (BB_*SS_)
#define MOUT (BB_*SP_)

// Scratch: q/k/v/ctx hold tf32 bit patterns; weights pre-converted AND
// pre-swizzled into mma-fragment order.
__device__ uint32_t g_q[BB_*HH_*SP_*DD_];     // [B,H,S',D] tf32 bits
__device__ uint32_t g_k[BB_*HH_*SP_*DD_];
__device__ uint32_t g_v[BB_*HH_*SP_*DD_];
__device__ uint32_t g_ctx[BB_*SP_*EE_];       // [B,S',E]  tf32 bits
__device__ uint32_t g_wqkv[192*EE_];          // fragment-ordered [Wq;Wk;Wv]
__device__ uint32_t g_wo[EE_*EE_];            // fragment-ordered Wo (128-wide n-blocks)

// ---------------------------------------------------------------------------
// helpers
// ---------------------------------------------------------------------------
__device__ __forceinline__ uint32_t f2tf32(float f) {
    uint32_t u;
    asm("cvt.rna.tf32.f32 %0, %1;" : "=r"(u) : "f"(f));
    return u;
}

__device__ __forceinline__ void mma_tf32(float c[4], const uint32_t a[4], const uint32_t b[2]) {
    asm volatile(
        "mma.sync.aligned.m16n8k8.row.col.f32.tf32.tf32.f32 "
        "{%0,%1,%2,%3}, {%4,%5,%6,%7}, {%8,%9}, {%0,%1,%2,%3};\n"
        : "+f"(c[0]), "+f"(c[1]), "+f"(c[2]), "+f"(c[3])
        : "r"(a[0]), "r"(a[1]), "r"(a[2]), "r"(a[3]), "r"(b[0]), "r"(b[1]));
}

__device__ __forceinline__ void ldsm_x4(uint32_t r[4], uint32_t addr) {
    asm volatile("ldmatrix.sync.aligned.m8n8.x4.shared.b16 {%0,%1,%2,%3}, [%4];"
                 : "=r"(r[0]), "=r"(r[1]), "=r"(r[2]), "=r"(r[3]) : "r"(addr));
}

__device__ __forceinline__ uint32_t smem_u32(const void* p) {
    return (uint32_t)__cvta_generic_to_shared(p);
}
#define CP16(dst, src) asm volatile("cp.async.cg.shared.global [%0], [%1], 16;\n" :: "r"(dst), "l"(src))
#define CP_COMMIT()    asm volatile("cp.async.commit_group;\n" ::: "memory")
#define CP_WAIT1()     asm volatile("cp.async.wait_group 1;\n" ::: "memory")
#define CP_WAIT0()     asm volatile("cp.async.wait_group 0;\n" ::: "memory")

#define S20 20   // smem row stride (80B): LDSM phases conflict-free, 16B-aligned

// Fragment-pair tile: 16 n-rows x 8 k, 128 u32.
__device__ __forceinline__ int frag_idx(int n16, int k8) {
    return ((n16 & 7) * 4 + (k8 & 3)) * 4 + ((n16 >> 3) << 1) + (k8 >> 2);
}

// ---------------------------------------------------------------------------
// Kernel 0: pre-convert + pre-swizzle weights (once per launch, ~5us)
// ---------------------------------------------------------------------------
__global__ __launch_bounds__(256)
void cvt_weights(const float* __restrict__ Wq, const float* __restrict__ Wk,
                 const float* __restrict__ Wv, const float* __restrict__ Wo)
{
    const int idx = blockIdx.x * 256 + threadIdx.x;   // 0..65535
    const int row = idx >> 10;
    const int k   = idx & 1023;
    const int it  = k >> 4;
    const int ks  = (k >> 3) & 1;
    const int k8  = k & 7;

    {
        const float* Ws[3] = { Wq, Wk, Wv };
        #pragma unroll
        for (int mat = 0; mat < 3; mat++) {
            int n = mat * 64 + row;
            int addr = ((it * 2 + ks) * 12 + (n >> 4)) * 128 + frag_idx(n & 15, k8);
            g_wqkv[addr] = f2tf32(Ws[mat][row * 1024 + k]);
        }
    }
    #pragma unroll
    for (int j = 0; j < 16; j++) {
        int e  = idx + j * 65536;
        int n  = e >> 10;
        int kk = e & 1023;
        int it2 = kk >> 4, ks2 = (kk >> 3) & 1, k82 = kk & 7;
        int nb = n >> 7, nn = n & 127;
        int addr = (((nb * 64 + it2) * 2 + ks2) * 8 + (nn >> 4)) * 128 + frag_idx(nn & 15, k82);
        g_wo[addr] = f2tf32(Wo[(size_t)n * 1024 + kk]);
    }
}

// ---------------------------------------------------------------------------
// Kernel 1: fused QKV projection (R12 champion).  BM=64, BN=192, BK=16,
// 256 thr / 8 warps, warp tile 32m x 48n, 3-stage cp.async.  Grid 512.
// ---------------------------------------------------------------------------
#define QKV_ASTG (64 * S20)    // 1280 u32
#define QKV_BSTG 3072          // u32
#define QKV_SMEM ((3 * QKV_ASTG + 3 * QKV_BSTG) * 4)   // 52.2 KB

__global__ __launch_bounds__(256)
void qkv_mma(const float* __restrict__ x,
             const float* __restrict__ bq, const float* __restrict__ bk,
             const float* __restrict__ bv)
{
    extern __shared__ uint32_t sm[];
    uint32_t* As = sm;                      // 3 stages of [64][S20]
    uint32_t* Bs = sm + 3 * QKV_ASTG;       // 3 stages of 3072 (fragment order)

    const int tid  = threadIdx.x;
    const int warp = tid >> 5;
    const int lane = tid & 31;
    const int wm   = warp >> 2;           // 0..1
    const int wn   = warp & 3;            // 0..3
    const int m0   = blockIdx.x * 64;
    const int lq   = lane >> 2;
    const int lr   = lane & 3;

    const int lt       = lane >> 3;
    const int lrw      = lane & 7;
    const int arow_off = (lt & 1) * 8 + lrw;
    const int akoff    = (lt >> 1) * 4;
    uint32_t a_ldsm[3];
    #pragma unroll
    for (int s = 0; s < 3; s++)
        a_ldsm[s] = smem_u32(&As[s * QKV_ASTG + (wm * 32 + arow_off) * S20 + akoff]);

    const int arow = tid >> 2;
    const int ac4  = (tid & 3) * 4;
    const float* a_src = x + (size_t)(m0 + arow) * 1024 + ac4;
    uint32_t a_dst[3];
    #pragma unroll
    for (int s = 0; s < 3; s++)
        a_dst[s] = smem_u32(&As[s * QKV_ASTG + arow * S20 + ac4]);

    uint32_t b_dst[3][3];
    #pragma unroll
    for (int s = 0; s < 3; s++)
        #pragma unroll
        for (int t = 0; t < 3; t++)
            b_dst[t][s] = smem_u32(&Bs[s * QKV_BSTG + (t * 256 + tid) * 4]);

    float acc[2][6][4];
    #pragma unroll
    for (int mt = 0; mt < 2; mt++)
        #pragma unroll
        for (int nt = 0; nt < 6; nt++)
            #pragma unroll
            for (int e = 0; e < 4; e++) acc[mt][nt][e] = 0.f;

    #pragma unroll
    for (int s = 0; s < 2; s++) {
        CP16(a_dst[s], a_src + s * 16);
        #pragma unroll
        for (int t = 0; t < 3; t++)
            CP16(b_dst[t][s], g_wqkv + s * QKV_BSTG + (t * 256 + tid) * 4);
        CP_COMMIT();
    }

    for (int it = 0; it < 64; ++it) {
        CP_WAIT1();
        __syncthreads();

        if (it + 2 < 64) {
            int s = (it + 2) % 3;
            CP16(a_dst[s], a_src + (it + 2) * 16);
            #pragma unroll
            for (int t = 0; t < 3; t++)
                CP16(b_dst[t][s], g_wqkv + (it + 2) * QKV_BSTG + (t * 256 + tid) * 4);
        }
        CP_COMMIT();

        const int cur = it % 3;
        const uint32_t* Bc = Bs + cur * QKV_BSTG;
        const uint32_t  Ab = a_ldsm[cur];

        #pragma unroll
        for (int ks = 0; ks < 2; ks++) {
            uint32_t af[2][4];
            #pragma unroll
            for (int mt = 0; mt < 2; mt++) {
                uint32_t raw[4];
                ldsm_x4(raw, Ab + (uint32_t)((mt * 16 * S20 + ks * 8) * 4));
                af[mt][0] = f2tf32(__uint_as_float(raw[0]));
                af[mt][1] = f2tf32(__uint_as_float(raw[1]));
                af[mt][2] = f2tf32(__uint_as_float(raw[2]));
                af[mt][3] = f2tf32(__uint_as_float(raw[3]));
            }
            #pragma unroll
            for (int pl = 0; pl < 3; pl++) {
                uint4 bv = *(const uint4*)&Bc[(ks * 12 + wn * 3 + pl) * 128 + lane * 4];
                uint32_t bfe[2] = { bv.x, bv.y };
                uint32_t bfo[2] = { bv.z, bv.w };
                mma_tf32(acc[0][2*pl  ], af[0], bfe);
                mma_tf32(acc[1][2*pl  ], af[1], bfe);
                mma_tf32(acc[0][2*pl+1], af[0], bfo);
                mma_tf32(acc[1][2*pl+1], af[1], bfo);
            }
        }
    }

    #pragma unroll
    for (int mt = 0; mt < 2; mt++) {
        #pragma unroll
        for (int half = 0; half < 2; half++) {
            int m  = m0 + wm * 32 + mt * 16 + half * 8 + lq;
            int bb = m >> 13;
            int s  = m & 8191;
            int sp = s >> 4;
            int h  = s & 15;
            size_t rowoff = ((size_t)(bb * 16 + h) * 512 + sp) * 64;
            #pragma unroll
            for (int nt = 0; nt < 6; nt++) {
                int n   = wn * 48 + nt * 8 + 2 * lr;
                int mat = n >> 6;
                int nn  = n & 63;
                uint32_t* dst = (mat == 0) ? g_q : (mat == 1 ? g_k : g_v);
                const float* bias = (mat == 0) ? bq : (mat == 1 ? bk : bv);
                uint2 v;
                v.x = f2tf32(acc[mt][nt][half * 2 + 0] + bias[nn]);
                v.y = f2tf32(acc[mt][nt][half * 2 + 1] + bias[nn + 1]);
                *(uint2*)(dst + rowoff + nn) = v;
            }
        }
    }
}

// ---------------------------------------------------------------------------
// Kernel 2: attention.  K-frags via ldmatrix.x4 (R12); K/V staging now via
// double-buffered cp.async (one sync per tile, latency hidden behind compute).
// Same layout, same math order -> bit-identical results.
// ---------------------------------------------------------------------------
#define KSTR 68
#define VSTR 72
#define K_TSZ (64 * KSTR)      // 4352 u32 per K buffer
#define V_TSZ (64 * VSTR)      // 4608 u32 per V buffer
#define AT_SMEM ((2 * K_TSZ + 2 * V_TSZ) * 4)   // 71.7 KB

__global__ __launch_bounds__(256)
void attn_mma()
{
    extern __shared__ __align__(16) uint32_t smA[];
    uint32_t* Kbuf = smA;                   // [2][K_TSZ]
    uint32_t* Vbuf = smA + 2 * K_TSZ;       // [2][V_TSZ]

    const int bh   = blockIdx.x;
    const int qt   = blockIdx.y;
    const int tid  = threadIdx.x;
    const int warp = tid >> 5;
    const int lane = tid & 31;
    const int lq   = lane >> 2;
    const int lr   = lane & 3;

    // K-LDSM per-lane address components (per buffer)
    const int g     = lane >> 3;
    const int rg    = lane & 7;
    const int sub_n = (g >> 1) * 8 + rg;
    const int koff  = (g & 1) * 4;
    uint32_t k_ldsm[2];
    k_ldsm[0] = smem_u32(&Kbuf[sub_n * KSTR + koff]);
    k_ldsm[1] = smem_u32(&Kbuf[K_TSZ + sub_n * KSTR + koff]);

    // staging assignments: 1024 16B-chunks per K (and V) tile, 4/thread
    const int srow = tid >> 4;              // rows handled: srow, srow+16, +32, +48
    const int sc4  = (tid & 15) << 2;
    uint32_t kst[2][4], vst[2][4];
    #pragma unroll
    for (int i = 0; i < 4; i++) {
        int row = srow + i * 16;
        #pragma unroll
        for (int s = 0; s < 2; s++) {
            kst[s][i] = smem_u32(&Kbuf[s * K_TSZ + row * KSTR + sc4]);
            vst[s][i] = smem_u32(&Vbuf[s * V_TSZ + row * VSTR + sc4]);
        }
    }

    const uint32_t* qbase = g_q + ((size_t)bh * 512 + qt * 128 + warp * 16) * 64;
    uint32_t qa[8][4];
    #pragma unroll
    for (int ks = 0; ks < 8; ks++) {
        qa[ks][0] = __float_as_uint(__uint_as_float(qbase[(size_t)lq       * 64 + ks * 8 + lr    ]) * 0.125f);
        qa[ks][1] = __float_as_uint(__uint_as_float(qbase[(size_t)(lq + 8) * 64 + ks * 8 + lr    ]) * 0.125f);
        qa[ks][2] = __float_as_uint(__uint_as_float(qbase[(size_t)lq       * 64 + ks * 8 + lr + 4]) * 0.125f);
        qa[ks][3] = __float_as_uint(__uint_as_float(qbase[(size_t)(lq + 8) * 64 + ks * 8 + lr + 4]) * 0.125f);
    }

    float o[8][4];
    #pragma unroll
    for (int nt = 0; nt < 8; nt++)
        #pragma unroll
        for (int e = 0; e < 4; e++) o[nt][e] = 0.f;
    float lsum0 = 0.f, lsum1 = 0.f;

    const uint32_t* kb = g_k + (size_t)bh * 512 * 64;
    const uint32_t* vb = g_v + (size_t)bh * 512 * 64;

    // prologue: stage tile 0 into buffer 0
    #pragma unroll
    for (int i = 0; i < 4; i++) {
        int off = (srow + i * 16) * 64 + sc4;     // row-major gmem offset
        CP16(kst[0][i], kb + off);
        CP16(vst[0][i], vb + off);
    }
    CP_COMMIT();

    for (int kt = 0; kt < 8; kt++) {
        CP_WAIT0();
        __syncthreads();

        // prefetch next tile into other buffer (overlaps this tile's compute)
        if (kt < 7) {
            const int nbuf = (kt + 1) & 1;
            const uint32_t* kn = kb + (size_t)(kt + 1) * 4096;
            const uint32_t* vn = vb + (size_t)(kt + 1) * 4096;
            #pragma unroll
            for (int i = 0; i < 4; i++) {
                int off = (srow + i * 16) * 64 + sc4;
                CP16(kst[nbuf][i], kn + off);
                CP16(vst[nbuf][i], vn + off);
            }
        }
        CP_COMMIT();

        const int buf = kt & 1;
        const uint32_t  Kb = k_ldsm[buf];
        const uint32_t* Vc = Vbuf + buf * V_TSZ;

        // S = Q @ K^T : K-frags via LDSM.x4
        float sc[8][4];
        #pragma unroll
        for (int nt = 0; nt < 8; nt++)
            sc[nt][0] = sc[nt][1] = sc[nt][2] = sc[nt][3] = 0.f;
        #pragma unroll
        for (int ks = 0; ks < 8; ks++) {
            #pragma unroll
            for (int ntp = 0; ntp < 4; ntp++) {
                uint32_t raw[4];
                ldsm_x4(raw, Kb + (uint32_t)((ntp * 16 * KSTR + ks * 8) * 4));
                uint32_t bf0[2] = { raw[0], raw[1] };
                uint32_t bf1[2] = { raw[2], raw[3] };
                mma_tf32(sc[2*ntp    ], qa[ks], bf0);
                mma_tf32(sc[2*ntp + 1], qa[ks], bf1);
            }
        }

        #pragma unroll
        for (int nt = 0; nt < 8; nt++) {
            float p0 = __expf(sc[nt][0]), p1 = __expf(sc[nt][1]);
            float p2 = __expf(sc[nt][2]), p3 = __expf(sc[nt][3]);
            sc[nt][0] = p0; sc[nt][1] = p1; sc[nt][2] = p2; sc[nt][3] = p3;
            lsum0 += p0 + p1;
            lsum1 += p2 + p3;
        }

        #pragma unroll
        for (int ks = 0; ks < 8; ks++) {
            int src  = (lane & ~3) | (lr >> 1);
            float t0 = __shfl_sync(0xffffffffu, sc[ks][0], src);
            float t1 = __shfl_sync(0xffffffffu, sc[ks][1], src);
            float t2 = __shfl_sync(0xffffffffu, sc[ks][2], src);
            float t3 = __shfl_sync(0xffffffffu, sc[ks][3], src);
            float u0 = __shfl_sync(0xffffffffu, sc[ks][0], src + 2);
            float u1 = __shfl_sync(0xffffffffu, sc[ks][1], src + 2);
            float u2 = __shfl_sync(0xffffffffu, sc[ks][2], src + 2);
            float u3 = __shfl_sync(0xffffffffu, sc[ks][3], src + 2);
            uint32_t pa[4];
            pa[0] = f2tf32((lr & 1) ? t1 : t0);
            pa[1] = f2tf32((lr & 1) ? t3 : t2);
            pa[2] = f2tf32((lr & 1) ? u1 : u0);
            pa[3] = f2tf32((lr & 1) ? u3 : u2);
            #pragma unroll
            for (int ntd = 0; ntd < 8; ntd++) {
                uint32_t bf[2];
                bf[0] = Vc[(ks * 8 + lr    ) * VSTR + ntd * 8 + lq];
                bf[1] = Vc[(ks * 8 + lr + 4) * VSTR + ntd * 8 + lq];
                mma_tf32(o[ntd], pa, bf);
            }
        }
        __syncthreads();   // all readers done before next prefetch overwrites
    }

    lsum0 += __shfl_xor_sync(0xffffffffu, lsum0, 1);
    lsum0 += __shfl_xor_sync(0xffffffffu, lsum0, 2);
    lsum1 += __shfl_xor_sync(0xffffffffu, lsum1, 1);
    lsum1 += __shfl_xor_sync(0xffffffffu, lsum1, 2);
    const float inv0 = 1.f / lsum0;
    const float inv1 = 1.f / lsum1;

    const int bb = bh >> 4, h = bh & 15;
    const int qrow0 = qt * 128 + warp * 16 + lq;
    uint32_t* out0 = g_ctx + ((size_t)(bb * 512 + qrow0)) * 1024 + h * 64;
    uint32_t* out1 = out0 + (size_t)8 * 1024;
    #pragma unroll
    for (int ntd = 0; ntd < 8; ntd++) {
        uint2 v0 = { f2tf32(o[ntd][0] * inv0), f2tf32(o[ntd][1] * inv0) };
        uint2 v1 = { f2tf32(o[ntd][2] * inv1), f2tf32(o[ntd][3] * inv1) };
        *(uint2*)(out0 + ntd * 8 + 2 * lr) = v0;
        *(uint2*)(out1 + ntd * 8 + 2 * lr) = v1;
    }
}

// ---------------------------------------------------------------------------
// Kernel 3: output projection (R12/R10 champion — 34.5us).
// BM=128, BN=128, BK=16, 512 thr / 16 warps, warp tile 32m x 32n.
// ---------------------------------------------------------------------------
#define OP_ASTG (128 * S20)   // 2560 u32
#define OP_BSTG 2048          // u32
#define OP_SMEM ((3 * OP_ASTG + 3 * OP_BSTG) * 4)

__global__ __launch_bounds__(512)
void outproj_mma(const float* __restrict__ bo, float* __restrict__ out)
{
    extern __shared__ uint32_t sm[];
    uint32_t* As = sm;
    uint32_t* Bs = sm + 3 * OP_ASTG;

    const int tid  = threadIdx.x;
    const int warp = tid >> 5;
    const int lane = tid & 31;
    const int wm   = warp >> 2;
    const int wn   = warp & 3;
    const int m0   = blockIdx.x * 128;
    const int nb   = blockIdx.y;
    const int lq   = lane >> 2;
    const int lr   = lane & 3;

    const int lt       = lane >> 3;
    const int lrw      = lane & 7;
    const int arow_off = (lt & 1) * 8 + lrw;
    const int akoff    = (lt >> 1) * 4;
    uint32_t a_ldsm[3];
    #pragma unroll
    for (int s = 0; s < 3; s++)
        a_ldsm[s] = smem_u32(&As[s * OP_ASTG + (wm * 32 + arow_off) * S20 + akoff]);

    const int arow = tid >> 2;
    const int ac4  = (tid & 3) * 4;
    const uint32_t* a_src = g_ctx + (size_t)(m0 + arow) * 1024 + ac4;
    uint32_t a_dst[3], b_dst[3];
    #pragma unroll
    for (int s = 0; s < 3; s++) {
        a_dst[s] = smem_u32(&As[s * OP_ASTG + arow * S20 + ac4]);
        b_dst[s] = smem_u32(&Bs[s * OP_BSTG + tid * 4]);
    }
    const uint32_t* b_base = g_wo + (size_t)nb * 64 * OP_BSTG;

    float acc[2][4][4];
    #pragma unroll
    for (int mt = 0; mt < 2; mt++)
        #pragma unroll
        for (int nt = 0; nt < 4; nt++)
            #pragma unroll
            for (int e = 0; e < 4; e++) acc[mt][nt][e] = 0.f;

    #pragma unroll
    for (int s = 0; s < 2; s++) {
        CP16(a_dst[s], a_src + s * 16);
        CP16(b_dst[s], b_base + s * OP_BSTG + tid * 4);
        CP_COMMIT();
    }

    for (int it = 0; it < 64; ++it) {
        CP_WAIT1();
        __syncthreads();

        if (it + 2 < 64) {
            int s = (it + 2) % 3;
            CP16(a_dst[s], a_src + (it + 2) * 16);
            CP16(b_dst[s], b_base + (size_t)(it + 2) * OP_BSTG + tid * 4);
        }
        CP_COMMIT();

        const int cur = it % 3;
        const uint32_t* Bc = Bs + cur * OP_BSTG;
        const uint32_t  Ab = a_ldsm[cur];

        #pragma unroll
        for (int ks = 0; ks < 2; ks++) {
            uint32_t af[2][4];
            #pragma unroll
            for (int mt = 0; mt < 2; mt++)
                ldsm_x4(af[mt], Ab + (uint32_t)((mt * 16 * S20 + ks * 8) * 4));
            #pragma unroll
            for (int pl = 0; pl < 2; pl++) {
                uint4 bv = *(const uint4*)&Bc[(ks * 8 + wn * 2 + pl) * 128 + lane * 4];
                uint32_t bfe[2] = { bv.x, bv.y };
                uint32_t bfo[2] = { bv.z, bv.w };
                mma_tf32(acc[0][2*pl  ], af[0], bfe);
                mma_tf32(acc[1][2*pl  ], af[1], bfe);
                mma_tf32(acc[0][2*pl+1], af[0], bfo);
                mma_tf32(acc[1][2*pl+1], af[1], bfo);
            }
        }
    }

    #pragma unroll
    for (int mt = 0; mt < 2; mt++) {
        #pragma unroll
        for (int half = 0; half < 2; half++) {
            int m = m0 + wm * 32 + mt * 16 + half * 8 + lq;
            float* rowp = out + (size_t)m * 1024 + nb * 128;
            #pragma unroll
            for (int nt = 0; nt < 4; nt++) {
                int n = wn * 32 + nt * 8 + 2 * lr;
                float2 v;
                v.x = acc[mt][nt][half * 2 + 0] + bo[nb * 128 + n];
                v.y = acc[mt][nt][half * 2 + 1] + bo[nb * 128 + n + 1];
                *(float2*)(rowp + n) = v;
            }
        }
    }
}

// ---------------------------------------------------------------------------
extern "C" void kernel_launch(void* const* d_in, const int* in_sizes, int n_in,
                              void* d_out, int out_size)
{
    const float* x  = (const float*)d_in[0];
    const float* Wq = (const float*)d_in[1];
    const float* bq = (const float*)d_in[2];
    const float* Wk = (const float*)d_in[3];
    const float* bk = (const float*)d_in[4];
    const float* Wv = (const float*)d_in[5];
    const float* bv = (const float*)d_in[6];
    const float* Wo = (const float*)d_in[7];
    const float* bo = (const float*)d_in[8];
    float* out = (float*)d_out;

    static bool attr_done = false;
    if (!attr_done) {
        cudaFuncSetAttribute(qkv_mma, cudaFuncAttributeMaxDynamicSharedMemorySize, QKV_SMEM);
        cudaFuncSetAttribute(attn_mma, cudaFuncAttributeMaxDynamicSharedMemorySize, AT_SMEM);
        cudaFuncSetAttribute(outproj_mma, cudaFuncAttributeMaxDynamicSharedMemorySize, OP_SMEM);
        attr_done = true;
    }

    cvt_weights<<<256, 256>>>(Wq, Wk, Wv, Wo);

    qkv_mma<<<MQKV / 64, 256, QKV_SMEM>>>(x, bq, bk, bv);

    dim3 g2(BB_ * HH_, SP_ / 128);
    attn_mma<<<g2, 256, AT_SMEM>>>();

    dim3 g3(MOUT / 128, EE_ / 128);
    outproj_mma<<<g3, 512, OP_SMEM>>>(bo, out);
}